// round 16
// baseline (speedup 1.0000x reference)
#include <cuda_runtime.h>
#include <cuda_bf16.h>
#include <cstdint>

#define U_    339
#define S_    5825
#define N_    6164
#define D_    128
#define H_    64
#define NNZ1_ 200000
#define B_    500000
#define EPS_  1e-5f

#define UP 352          // padded U rows
#define SP 5856         // padded S rows (183*32)

// ---------------- device scratch (static, zero-initialized; pads never written) ----------------
__device__ float g_D [UP * SP];      // dense A_us (u-major)
__device__ float g_DT[SP * UP];      // dense A_su (s-major)
__device__ float g_Q [2 * 128 * 64]; // side0 = Qu (uH,W1top), side1 = Qi (iH,W1bot)
__device__ float g_Bu [UP * 64], g_Bs [SP * 64];
__device__ float g_Y1u[UP * 64], g_Y1s[SP * 64];
__device__ float g_Y2u[UP * 64], g_Y2s[SP * 64];
__device__ float g_ABu[UP * 64], g_ABs[SP * 64];

// ---------------- helpers ----------------
__device__ __forceinline__ uint32_t to_tf32(float f) {
    uint32_t r;
    asm("cvt.rna.tf32.f32 %0, %1;" : "=r"(r) : "f"(f));
    return r;
}
__device__ __forceinline__ void mma16n8k8(float c[4], uint32_t a0, uint32_t a1,
                                          uint32_t a2, uint32_t a3,
                                          uint32_t b0, uint32_t b1) {
    asm volatile(
        "mma.sync.aligned.m16n8k8.row.col.f32.tf32.tf32.f32 "
        "{%0,%1,%2,%3}, {%4,%5,%6,%7}, {%8,%9}, {%0,%1,%2,%3};"
        : "+f"(c[0]), "+f"(c[1]), "+f"(c[2]), "+f"(c[3])
        : "r"(a0), "r"(a1), "r"(a2), "r"(a3), "r"(b0), "r"(b1));
}

// ---------------- K0: hyperQ (Q[side] = H^T (H @ W1_half)) ----------------
__global__ void hyperQ_kernel(const float* __restrict__ uH, const float* __restrict__ iH,
                              const float* __restrict__ W1) {
    int side = blockIdx.x;
    int t = threadIdx.x;
    const float* __restrict__ Hp = side ? iH : uH;
    const float* __restrict__ W1p = W1 + side * 128 * 64;
    __shared__ float sH[32 * 128];
    __shared__ float sRW[32 * 64];
    for (int i = t; i < 32 * 128; i += 1024) sH[i] = Hp[i];
    __syncthreads();
    for (int o = t; o < 32 * 64; o += 1024) {
        int r = o >> 6, j = o & 63;
        float acc = 0.f;
        for (int b = 0; b < 128; b++) acc += sH[r * 128 + b] * W1p[b * 64 + j];
        sRW[o] = acc;
    }
    __syncthreads();
    for (int o = t; o < 128 * 64; o += 1024) {
        int a = o >> 6, j = o & 63;
        float acc = 0.f;
#pragma unroll
        for (int r = 0; r < 32; r++) acc += sH[r * 128 + a] * sRW[r * 64 + j];
        g_Q[side * 128 * 64 + o] = acc;
    }
}

// ---------------- K1: fused projB + densify + zero(Y1u) ----------------
// blocks [0,193): projB: Bu[r]=e0_u[r]@Qi, Bs[r]=e0_s[r]@Qu
// blocks [193,291): densify D/DT from u-half of COO (first NNZ1_ entries)
// blocks [291,297): zero Y1u
#define PJB 193
#define DFB 98
#define ZB0 6
#define PREPG (PJB + DFB + ZB0)
__global__ void __launch_bounds__(512)
prep_kernel(const float* __restrict__ uE, const float* __restrict__ iE,
            const int* __restrict__ adj_rows, const int* __restrict__ adj_cols,
            const float* __restrict__ adj_vals) {
    int tid = threadIdx.x;
    int bid = blockIdx.x;
    if (bid < PJB) {
        __shared__ float sE[32 * 128];
        int rb = bid * 32;
        for (int t = tid; t < 32 * 128; t += 512) {
            int r = rb + (t >> 7);
            float v = 0.f;
            if (r < U_) v = uE[r * 128 + (t & 127)];
            else if (r < N_) v = iE[(r - U_) * 128 + (t & 127)];
            sE[t] = v;
        }
        __syncthreads();
        int j = tid & 63;
        int rl0 = tid >> 6;     // 0..7
        for (int rl = rl0; rl < 32; rl += 8) {
            int r = rb + rl;
            if (r >= N_) break;
            const float* __restrict__ Qp = (r < U_) ? (g_Q + 128 * 64) : g_Q;  // u->Qi, s->Qu
            float acc = 0.f;
#pragma unroll 8
            for (int k = 0; k < 128; k++) acc += sE[rl * 128 + k] * Qp[k * 64 + j];
            if (r < U_) g_Bu[r * 64 + j] = acc;
            else        g_Bs[(r - U_) * 64 + j] = acc;
        }
    } else if (bid < PJB + DFB) {
        for (int i = (bid - PJB) * 512 + tid; i < NNZ1_; i += DFB * 512) {
            int u = adj_rows[i];
            int s = adj_cols[i] - U_;
            float v = adj_vals[i];
            g_D[u * SP + s] = v;
            g_DT[s * UP + u] = v;
        }
    } else {
        float4* z4 = (float4*)g_Y1u;
        const int n4 = UP * 64 / 4;
        for (int i = (bid - PJB - DFB) * 512 + tid; i < n4; i += ZB0 * 512)
            z4[i] = make_float4(0.f, 0.f, 0.f, 0.f);
    }
}

// ---------------- K2: one propagation pass (fused dense GEMMs) ----------------
// blocks [0,183):        G2: Ys[5856,64] = DT @ Xu   (full K=352, direct store)
// blocks [183,183+671):  G1: Yu[352,64] += D @ Xs    (split-K 61 x 96, atomicAdd)
// blocks [854,860):      zero Zu (next pass's atomic target), if non-null
#define G2B 183
#define G1B 671      // 11 m-tiles x 61 k-chunks
#define ZBP 6
#define PASSG (G2B + G1B + ZBP)   // 860
__global__ void __launch_bounds__(128)
pass_kernel(const float* __restrict__ Xu, const float* __restrict__ Xs,
            float* __restrict__ Yu, float* __restrict__ Ys, float* __restrict__ Zu) {
    int tid = threadIdx.x;
    int bid = blockIdx.x;
    if (bid >= G2B + G1B) {
        if (Zu) {
            float4* z4 = (float4*)Zu;
            const int n4 = UP * 64 / 4;
            for (int i = (bid - G2B - G1B) * 128 + tid; i < n4; i += ZBP * 128)
                z4[i] = make_float4(0.f, 0.f, 0.f, 0.f);
        }
        return;
    }
    __shared__ float sAT[32][36];
    __shared__ float sB[32][68];

    const float* __restrict__ A;
    const float* __restrict__ B;
    int lda, m0, k0, nsub;
    bool atom;
    if (bid < G2B) {
        A = g_DT; lda = UP; B = Xu; m0 = bid * 32; k0 = 0; nsub = UP / 32; atom = false;
    } else {
        int b2 = bid - G2B;
        int mt = b2 / 61, kc = b2 % 61;
        A = g_D; lda = SP; B = Xs; m0 = mt * 32; k0 = kc * 96; nsub = 3; atom = true;
    }
    int tc4 = (tid & 15) * 4;   // col group
    int tr4 = (tid >> 4) * 4;   // row group
    float acc[4][4] = {};

    for (int sc = 0; sc < nsub; sc++) {
        int kb = k0 + sc * 32;
        // stage B tile [32 k][64 n]
#pragma unroll
        for (int i = 0; i < 4; i++) {
            int e = tid + i * 128;           // 0..511 float4 slots
            int row = e >> 4, c4 = (e & 15) * 4;
            *(float4*)&sB[row][c4] = *(const float4*)&B[(kb + row) * 64 + c4];
        }
        // stage A tile transposed: sAT[k][m]
#pragma unroll
        for (int i = 0; i < 2; i++) {
            int e = tid + i * 128;           // 0..255 float4 slots
            int m = e >> 3, c4 = (e & 7) * 4;
            float4 v = *(const float4*)&A[(m0 + m) * lda + kb + c4];
            sAT[c4 + 0][m] = v.x;
            sAT[c4 + 1][m] = v.y;
            sAT[c4 + 2][m] = v.z;
            sAT[c4 + 3][m] = v.w;
        }
        __syncthreads();
#pragma unroll
        for (int k = 0; k < 32; k++) {
            float4 b = *(float4*)&sB[k][tc4];
            float4 a = *(float4*)&sAT[k][tr4];
            acc[0][0] += a.x * b.x; acc[0][1] += a.x * b.y; acc[0][2] += a.x * b.z; acc[0][3] += a.x * b.w;
            acc[1][0] += a.y * b.x; acc[1][1] += a.y * b.y; acc[1][2] += a.y * b.z; acc[1][3] += a.y * b.w;
            acc[2][0] += a.z * b.x; acc[2][1] += a.z * b.y; acc[2][2] += a.z * b.z; acc[2][3] += a.z * b.w;
            acc[3][0] += a.w * b.x; acc[3][1] += a.w * b.y; acc[3][2] += a.w * b.z; acc[3][3] += a.w * b.w;
        }
        __syncthreads();
    }

    if (!atom) {
#pragma unroll
        for (int i = 0; i < 4; i++)
            *(float4*)&Ys[(m0 + tr4 + i) * 64 + tc4] =
                make_float4(acc[i][0], acc[i][1], acc[i][2], acc[i][3]);
    } else {
#pragma unroll
        for (int i = 0; i < 4; i++)
#pragma unroll
            for (int j = 0; j < 4; j++)
                atomicAdd(&Yu[(m0 + tr4 + i) * 64 + tc4 + j], acc[i][j]);
    }
}

// ---------------- K3: persistent fused MLP, layer-2 via mma.sync tf32 ----------------
#define XS 68
#define WS 72
#define NT_ ((B_ + 127) / 128)
#define MLP_GRID 592

__global__ void __launch_bounds__(128)
mlp_kernel(const int* __restrict__ uIdx, const int* __restrict__ sIdx,
           const float* __restrict__ b1,
           const float* __restrict__ g1, const float* __restrict__ be1,
           const float* __restrict__ W2, const float* __restrict__ b2,
           const float* __restrict__ g2, const float* __restrict__ be2,
           const float* __restrict__ W3, const float* __restrict__ b3,
           float* __restrict__ out) {
    extern __shared__ uint32_t sX[];          // [128 * XS]
    __shared__ uint32_t sW[64 * WS];
    __shared__ float4 sEp[64];
    __shared__ float sg1[64], sbe1[64], sb1v[64];

    int tid = threadIdx.x;
    for (int idx = tid; idx < 64 * 64; idx += 128) {
        int k = idx >> 6, n = idx & 63;
        sW[k * WS + n] = to_tf32(W2[idx]);
    }
    if (tid < 64) {
        sg1[tid] = g1[tid]; sbe1[tid] = be1[tid]; sb1v[tid] = b1[tid];
        sEp[tid] = make_float4(b2[tid], g2[tid], be2[tid], W3[tid]);
    }
    __syncthreads();
    float bb = b3[0];

    int wid = tid >> 5;
    int lane = tid & 31;
    int gid = lane >> 2;
    int tig = lane & 3;
    uint32_t* rowp = sX + tid * XS;

    for (int tile = blockIdx.x; tile < NT_; tile += MLP_GRID) {
        int r = tile * 128 + tid;

        {
            float x[64];
            float sum = 0.f;
            if (r < B_) {
                int u = uIdx[r], s = sIdx[r];
                const float4* __restrict__ pa = (const float4*)(g_ABu + u * H_);
                const float4* __restrict__ pb = (const float4*)(g_ABs + s * H_);
#pragma unroll
                for (int q = 0; q < 16; q++) {
                    float4 a = pa[q];
                    float4 b = pb[q];
                    float v0 = a.x + b.x + sb1v[4 * q];
                    float v1 = a.y + b.y + sb1v[4 * q + 1];
                    float v2 = a.z + b.z + sb1v[4 * q + 2];
                    float v3 = a.w + b.w + sb1v[4 * q + 3];
                    x[4 * q] = v0; x[4 * q + 1] = v1; x[4 * q + 2] = v2; x[4 * q + 3] = v3;
                    sum += v0 + v1 + v2 + v3;
                }
            } else {
#pragma unroll
                for (int k = 0; k < 64; k++) x[k] = 0.f;
            }
            float mu = sum * (1.f / 64.f);
            float var = 0.f;
#pragma unroll
            for (int k = 0; k < 64; k++) { float d = x[k] - mu; var += d * d; }
            float inv = rsqrtf(var * (1.f / 64.f) + EPS_);
#pragma unroll
            for (int q = 0; q < 16; q++) {
                uint4 w;
                w.x = to_tf32(fmaxf(0.f, (x[4 * q]     - mu) * inv * sg1[4 * q]     + sbe1[4 * q]));
                w.y = to_tf32(fmaxf(0.f, (x[4 * q + 1] - mu) * inv * sg1[4 * q + 1] + sbe1[4 * q + 1]));
                w.z = to_tf32(fmaxf(0.f, (x[4 * q + 2] - mu) * inv * sg1[4 * q + 2] + sbe1[4 * q + 2]));
                w.w = to_tf32(fmaxf(0.f, (x[4 * q + 3] - mu) * inv * sg1[4 * q + 3] + sbe1[4 * q + 3]));
                *(uint4*)(rowp + 4 * q) = w;
            }
        }
        __syncwarp();

#pragma unroll
        for (int mt = 0; mt < 2; mt++) {
            int mb = (wid * 2 + mt) * 16;
            const uint32_t* arow0 = sX + (mb + gid) * XS;
            const uint32_t* arow1 = sX + (mb + gid + 8) * XS;

            float c[8][4];
#pragma unroll
            for (int no = 0; no < 8; no++) {
                c[no][0] = 0.f; c[no][1] = 0.f; c[no][2] = 0.f; c[no][3] = 0.f;
            }
#pragma unroll
            for (int ko = 0; ko < 8; ko++) {
                int k0 = ko * 8;
                uint32_t a0 = arow0[k0 + tig];
                uint32_t a1 = arow1[k0 + tig];
                uint32_t a2 = arow0[k0 + tig + 4];
                uint32_t a3 = arow1[k0 + tig + 4];
                const uint32_t* bk0 = sW + (k0 + tig) * WS;
                const uint32_t* bk1 = sW + (k0 + tig + 4) * WS;
#pragma unroll
                for (int no = 0; no < 8; no++) {
                    uint32_t b0 = bk0[no * 8 + gid];
                    uint32_t b1r = bk1[no * 8 + gid];
                    mma16n8k8(c[no], a0, a1, a2, a3, b0, b1r);
                }
            }

            float ep_g2[16], ep_be2[16], ep_w3[16];
            float s0 = 0.f, q0 = 0.f, s1 = 0.f, q1 = 0.f;
#pragma unroll
            for (int no = 0; no < 8; no++) {
                int col = no * 8 + 2 * tig;
                float4 e0 = sEp[col];
                float4 e1 = sEp[col + 1];
                ep_g2[2 * no] = e0.y;  ep_be2[2 * no] = e0.z;  ep_w3[2 * no] = e0.w;
                ep_g2[2 * no + 1] = e1.y; ep_be2[2 * no + 1] = e1.z; ep_w3[2 * no + 1] = e1.w;
                c[no][0] += e0.x; c[no][1] += e1.x;
                c[no][2] += e0.x; c[no][3] += e1.x;
                s0 += c[no][0] + c[no][1];
                q0 += c[no][0] * c[no][0] + c[no][1] * c[no][1];
                s1 += c[no][2] + c[no][3];
                q1 += c[no][2] * c[no][2] + c[no][3] * c[no][3];
            }
            s0 += __shfl_xor_sync(0xffffffffu, s0, 1);
            s0 += __shfl_xor_sync(0xffffffffu, s0, 2);
            q0 += __shfl_xor_sync(0xffffffffu, q0, 1);
            q0 += __shfl_xor_sync(0xffffffffu, q0, 2);
            s1 += __shfl_xor_sync(0xffffffffu, s1, 1);
            s1 += __shfl_xor_sync(0xffffffffu, s1, 2);
            q1 += __shfl_xor_sync(0xffffffffu, q1, 1);
            q1 += __shfl_xor_sync(0xffffffffu, q1, 2);

            float mu0 = s0 * (1.f / 64.f);
            float var0 = fmaxf(q0 * (1.f / 64.f) - mu0 * mu0, 0.f);
            float inv0 = rsqrtf(var0 + EPS_);
            float mu1 = s1 * (1.f / 64.f);
            float var1 = fmaxf(q1 * (1.f / 64.f) - mu1 * mu1, 0.f);
            float inv1 = rsqrtf(var1 + EPS_);

            float d0 = 0.f, d1 = 0.f;
#pragma unroll
            for (int no = 0; no < 8; no++) {
#pragma unroll
                for (int j = 0; j < 2; j++) {
                    int p = 2 * no + j;
                    float h0 = fmaxf(0.f, (c[no][j]     - mu0) * inv0 * ep_g2[p] + ep_be2[p]);
                    float h1 = fmaxf(0.f, (c[no][2 + j] - mu1) * inv1 * ep_g2[p] + ep_be2[p]);
                    d0 += h0 * ep_w3[p];
                    d1 += h1 * ep_w3[p];
                }
            }
            d0 += __shfl_xor_sync(0xffffffffu, d0, 1);
            d0 += __shfl_xor_sync(0xffffffffu, d0, 2);
            d1 += __shfl_xor_sync(0xffffffffu, d1, 1);
            d1 += __shfl_xor_sync(0xffffffffu, d1, 2);

            if (tig == 0) {
                int r0 = tile * 128 + mb + gid;
                int r1 = r0 + 8;
                if (r0 < B_) out[r0] = d0 + bb;
                if (r1 < B_) out[r1] = d1 + bb;
            }
        }
        __syncwarp();
    }
}

// ---------------- launcher ----------------
extern "C" void kernel_launch(void* const* d_in, const int* in_sizes, int n_in,
                              void* d_out, int out_size) {
    const float* uE  = (const float*)d_in[0];
    const float* iE  = (const float*)d_in[1];
    const float* uH  = (const float*)d_in[2];
    const float* iH  = (const float*)d_in[3];
    const float* W1  = (const float*)d_in[4];
    const float* b1  = (const float*)d_in[5];
    const float* g1  = (const float*)d_in[6];
    const float* be1 = (const float*)d_in[7];
    const float* W2  = (const float*)d_in[8];
    const float* b2  = (const float*)d_in[9];
    const float* g2  = (const float*)d_in[10];
    const float* be2 = (const float*)d_in[11];
    const float* W3  = (const float*)d_in[12];
    const float* b3  = (const float*)d_in[13];
    const float* adj_vals = (const float*)d_in[14];
    const int*   adj_rows = (const int*)d_in[15];
    const int*   adj_cols = (const int*)d_in[16];
    const int*   uIdx = (const int*)d_in[17];
    const int*   sIdx = (const int*)d_in[18];
    float* out = (float*)d_out;

    static int attr_set = 0;
    if (!attr_set) {
        cudaFuncSetAttribute(mlp_kernel, cudaFuncAttributeMaxDynamicSharedMemorySize,
                             128 * XS * 4);
        attr_set = 1;
    }

    // device pointers to the __device__ buffers (for pass kernel args)
    static float *pBu = nullptr, *pBs, *pY1u, *pY1s, *pY2u, *pY2s, *pABu, *pABs;
    if (!pBu) {
        cudaGetSymbolAddress((void**)&pBu,  g_Bu);
        cudaGetSymbolAddress((void**)&pBs,  g_Bs);
        cudaGetSymbolAddress((void**)&pY1u, g_Y1u);
        cudaGetSymbolAddress((void**)&pY1s, g_Y1s);
        cudaGetSymbolAddress((void**)&pY2u, g_Y2u);
        cudaGetSymbolAddress((void**)&pY2s, g_Y2s);
        cudaGetSymbolAddress((void**)&pABu, g_ABu);
        cudaGetSymbolAddress((void**)&pABs, g_ABs);
    }

    hyperQ_kernel<<<2, 1024>>>(uH, iH, W1);
    prep_kernel<<<PREPG, 512>>>(uE, iE, adj_rows, adj_cols, adj_vals);
    pass_kernel<<<PASSG, 128>>>(pBu,  pBs,  pY1u, pY1s, pY2u);   // pass 1 (+zero Y2u)
    pass_kernel<<<PASSG, 128>>>(pY1u, pY1s, pY2u, pY2s, pABu);   // pass 2 (+zero ABu)
    pass_kernel<<<PASSG, 128>>>(pY2u, pY2s, pABu, pABs, nullptr);// pass 3
    mlp_kernel<<<MLP_GRID, 128, 128 * XS * 4>>>(uIdx, sIdx, b1, g1, be1, W2, b2,
                                                g2, be2, W3, b3, out);
}